// round 1
// baseline (speedup 1.0000x reference)
#include <cuda_runtime.h>
#include <cuda_bf16.h>
#include <math.h>

#define DIM     1024
#define HEADS   16
#define DHEAD   64
#define INNER   1024
#define BATCH   4
#define NTOK    4096
#define MTOT    (BATCH * NTOK)      // 16384
#define QKVN    (3 * INNER)         // 3072
#define NSPLIT  16

// Scratch (device globals: no runtime allocation allowed)
__device__ float g_qkv[(size_t)MTOT * QKVN];                         // 192 MB
__device__ float g_part[(size_t)NSPLIT * BATCH * HEADS * DHEAD * DHEAD]; // 16 MB
__device__ float g_C[(size_t)BATCH * HEADS * DHEAD * DHEAD];         // 1 MB
__device__ float g_u[(size_t)MTOT * INNER];                          // 64 MB

// ---------------------------------------------------------------------------
// SGEMM: C[M,N] = A[M,K] @ B[K,N] (+ bias[N]).  Row-major, all dims divide tiles.
// BM=BN=128, BK=16, 256 threads, 8x8 micro-tile.
// ---------------------------------------------------------------------------
#define BM 128
#define BN 128
#define BK 16
#define TM 8
#define TN 8

__global__ __launch_bounds__(256) void sgemm_kernel(
    const float* __restrict__ A, const float* __restrict__ Bm,
    const float* __restrict__ bias, float* __restrict__ C,
    int M, int N, int K)
{
    __shared__ float As[BK][BM];
    __shared__ float Bs[BK][BN];

    const int tid = threadIdx.x;
    const int bx = blockIdx.x;   // N direction
    const int by = blockIdx.y;   // M direction
    const int tx = tid % 16;
    const int ty = tid / 16;

    float acc[TM][TN];
#pragma unroll
    for (int m = 0; m < TM; m++)
#pragma unroll
        for (int n = 0; n < TN; n++) acc[m][n] = 0.f;

    const float* Ab = A + (size_t)by * BM * K;
    const float* Bb = Bm + (size_t)bx * BN;

    for (int k0 = 0; k0 < K; k0 += BK) {
        // Load A tile (BM x BK) transposed into As[BK][BM]
#pragma unroll
        for (int i = tid * 4; i < BM * BK; i += 1024) {
            int row = i / BK, col = i % BK;
            float4 t = *reinterpret_cast<const float4*>(Ab + (size_t)row * K + k0 + col);
            As[col + 0][row] = t.x;
            As[col + 1][row] = t.y;
            As[col + 2][row] = t.z;
            As[col + 3][row] = t.w;
        }
        // Load B tile (BK x BN)
#pragma unroll
        for (int i = tid * 4; i < BK * BN; i += 1024) {
            int row = i / BN, col = i % BN;
            *reinterpret_cast<float4*>(&Bs[row][col]) =
                *reinterpret_cast<const float4*>(Bb + (size_t)(k0 + row) * N + col);
        }
        __syncthreads();

#pragma unroll
        for (int kk = 0; kk < BK; kk++) {
            float ra[TM], rb[TN];
#pragma unroll
            for (int m = 0; m < TM; m++) ra[m] = As[kk][ty * TM + m];
#pragma unroll
            for (int n = 0; n < TN; n++) rb[n] = Bs[kk][tx * TN + n];
#pragma unroll
            for (int m = 0; m < TM; m++)
#pragma unroll
                for (int n = 0; n < TN; n++)
                    acc[m][n] += ra[m] * rb[n];
        }
        __syncthreads();
    }

    float bv[TN];
#pragma unroll
    for (int n = 0; n < TN; n++)
        bv[n] = bias ? bias[bx * BN + tx * TN + n] : 0.f;

#pragma unroll
    for (int m = 0; m < TM; m++) {
        int grow = by * BM + ty * TM + m;
        float* Crow = C + (size_t)grow * N + bx * BN + tx * TN;
#pragma unroll
        for (int n = 0; n < TN; n += 4) {
            float4 t;
            t.x = acc[m][n + 0] + bv[n + 0];
            t.y = acc[m][n + 1] + bv[n + 1];
            t.z = acc[m][n + 2] + bv[n + 2];
            t.w = acc[m][n + 3] + bv[n + 3];
            *reinterpret_cast<float4*>(Crow + n) = t;
        }
    }
}

// ---------------------------------------------------------------------------
// kv partial: for (b,h,split) accumulate kv[d][e] = sum_n k[n,d]*v[n,e]
// over a 256-token slice. Deterministic (no atomics).
// ---------------------------------------------------------------------------
#define KVCH 16

__global__ __launch_bounds__(256) void kv_partial_kernel(float* __restrict__ part)
{
    const int bh = blockIdx.x;      // 0..63
    const int split = blockIdx.y;   // 0..NSPLIT-1
    const int b = bh / HEADS, h = bh % HEADS;
    const int n0 = split * (NTOK / NSPLIT);

    __shared__ float ks[KVCH][DHEAD];
    __shared__ float vs[KVCH][DHEAD];

    const int tid = threadIdx.x;
    const int tx = tid % 16, ty = tid / 16;

    float acc[4][4];
#pragma unroll
    for (int i = 0; i < 4; i++)
#pragma unroll
        for (int j = 0; j < 4; j++) acc[i][j] = 0.f;

    const float* base = g_qkv + (size_t)b * NTOK * QKVN;

    for (int n = n0; n < n0 + NTOK / NSPLIT; n += KVCH) {
        {   // 16x64 = 1024 floats: one float4 per thread for each of k, v
            int i = tid * 4;
            int r = i / DHEAD, c = i % DHEAD;
            const float* p = base + (size_t)(n + r) * QKVN + h * DHEAD + c;
            *reinterpret_cast<float4*>(&ks[r][c]) = *reinterpret_cast<const float4*>(p + INNER);
            *reinterpret_cast<float4*>(&vs[r][c]) = *reinterpret_cast<const float4*>(p + 2 * INNER);
        }
        __syncthreads();
#pragma unroll
        for (int nn = 0; nn < KVCH; nn++) {
            float rk[4], rv[4];
#pragma unroll
            for (int i = 0; i < 4; i++) rk[i] = ks[nn][ty * 4 + i];
#pragma unroll
            for (int j = 0; j < 4; j++) rv[j] = vs[nn][tx * 4 + j];
#pragma unroll
            for (int i = 0; i < 4; i++)
#pragma unroll
                for (int j = 0; j < 4; j++)
                    acc[i][j] += rk[i] * rv[j];
        }
        __syncthreads();
    }

    float* out = part + ((size_t)split * BATCH * HEADS + bh) * (DHEAD * DHEAD);
#pragma unroll
    for (int i = 0; i < 4; i++)
#pragma unroll
        for (int j = 0; j < 4; j++)
            out[(ty * 4 + i) * DHEAD + tx * 4 + j] = acc[i][j];
}

// ---------------------------------------------------------------------------
// kv finalize: sum partials, row-normalize, fold gamma^2:
//   C[d][e] = gamma_h^2 * kv[d][e] / ||kv[d,:]||
// ---------------------------------------------------------------------------
__global__ void kv_finalize_kernel(const float* __restrict__ gamma)
{
    const int bh = blockIdx.x;   // 64 blocks
    const int d = threadIdx.x;   // 64 threads
    const int h = bh % HEADS;

    float row[DHEAD];
#pragma unroll
    for (int e = 0; e < DHEAD; e++) row[e] = 0.f;

    for (int s = 0; s < NSPLIT; s++) {
        const float* p = g_part + ((size_t)s * BATCH * HEADS + bh) * (DHEAD * DHEAD) + d * DHEAD;
#pragma unroll
        for (int e = 0; e < DHEAD; e++) row[e] += p[e];
    }
    float ss = 0.f;
#pragma unroll
    for (int e = 0; e < DHEAD; e++) ss += row[e] * row[e];

    const float g = gamma[h];
    const float scale = g * g / sqrtf(ss);

    float* out = g_C + (size_t)bh * DHEAD * DHEAD + d * DHEAD;
#pragma unroll
    for (int e = 0; e < DHEAD; e++) out[e] = row[e] * scale;
}

// ---------------------------------------------------------------------------
// apply: u[b,n, h*64+e] = (q[b,h,n,:] @ C[b,h]) / ||q[b,h,n,:]||
// One block per (b,h, 64-token chunk).
// ---------------------------------------------------------------------------
#define QPAD 68   // pad keeps float4 alignment (68*4 bytes = 16B multiple) and breaks bank conflicts

__global__ __launch_bounds__(256) void apply_kernel(float* __restrict__ u)
{
    const int bh = blockIdx.x;     // 64
    const int chunk = blockIdx.y;  // 64 chunks of 64 tokens
    const int b = bh / HEADS, h = bh % HEADS;

    __shared__ float Cs[DHEAD][DHEAD];
    __shared__ float qs[64][QPAD];
    __shared__ float inv[64];

    const int tid = threadIdx.x;
    const int n0 = chunk * 64;

    // Load C (4096 floats)
#pragma unroll
    for (int i = tid * 4; i < DHEAD * DHEAD; i += 1024)
        *reinterpret_cast<float4*>(&Cs[0][0] + i) =
            *reinterpret_cast<const float4*>(g_C + (size_t)bh * DHEAD * DHEAD + i);

    // Load q tile (64 tokens x 64)
#pragma unroll
    for (int i = tid * 4; i < 64 * DHEAD; i += 1024) {
        int t = i / DHEAD, d = i % DHEAD;
        *reinterpret_cast<float4*>(&qs[t][d]) =
            *reinterpret_cast<const float4*>(g_qkv + (size_t)(b * NTOK + n0 + t) * QKVN + h * DHEAD + d);
    }
    __syncthreads();

    if (tid < 64) {
        float ss = 0.f;
#pragma unroll
        for (int d = 0; d < DHEAD; d++) { float x = qs[tid][d]; ss += x * x; }
        inv[tid] = 1.0f / sqrtf(ss);
    }
    __syncthreads();

    const int tx = tid % 16, ty = tid / 16;
    float acc[4][4];
#pragma unroll
    for (int i = 0; i < 4; i++)
#pragma unroll
        for (int j = 0; j < 4; j++) acc[i][j] = 0.f;

#pragma unroll
    for (int d = 0; d < DHEAD; d++) {
        float rq[4], rc[4];
#pragma unroll
        for (int i = 0; i < 4; i++) rq[i] = qs[ty * 4 + i][d];
#pragma unroll
        for (int j = 0; j < 4; j++) rc[j] = Cs[d][tx * 4 + j];
#pragma unroll
        for (int i = 0; i < 4; i++)
#pragma unroll
            for (int j = 0; j < 4; j++)
                acc[i][j] += rq[i] * rc[j];
    }

#pragma unroll
    for (int i = 0; i < 4; i++) {
        int t = ty * 4 + i;
        float s = inv[t];
        float4 o;
        o.x = acc[i][0] * s; o.y = acc[i][1] * s; o.z = acc[i][2] * s; o.w = acc[i][3] * s;
        *reinterpret_cast<float4*>(u + (size_t)(b * NTOK + n0 + t) * INNER + h * DHEAD + tx * 4) = o;
    }
}

// ---------------------------------------------------------------------------
// GEMM variants reading scratch globals directly (scratch cannot be passed by
// symbol address cleanly inside capture; direct global refs are simplest)
// ---------------------------------------------------------------------------
__global__ __launch_bounds__(256) void sgemm_qkv_wrapper(const float* __restrict__ A,
                                                         const float* __restrict__ Bm)
{
    // unused; kept minimal — see kernel_launch (we pass symbol pointers instead)
}

extern "C" void kernel_launch(void* const* d_in, const int* in_sizes, int n_in,
                              void* d_out, int out_size)
{
    const float* x     = (const float*)d_in[0];
    const float* W_qkv = (const float*)d_in[1];
    const float* W_o   = (const float*)d_in[2];
    const float* b_o   = (const float*)d_in[3];
    const float* gamma = (const float*)d_in[4];
    float* out = (float*)d_out;

    // Resolve scratch addresses (host-side queries, legal under capture)
    static float* qkv_p = nullptr;
    static float* part_p = nullptr;
    static float* u_p = nullptr;
    if (!qkv_p) {
        cudaGetSymbolAddress((void**)&qkv_p, g_qkv);
        cudaGetSymbolAddress((void**)&part_p, g_part);
        cudaGetSymbolAddress((void**)&u_p, g_u);
    }

    // 1) qkv = x @ W_qkv           [16384,1024]x[1024,3072]
    sgemm_kernel<<<dim3(QKVN / BN, MTOT / BM), 256>>>(x, W_qkv, nullptr, qkv_p,
                                                      MTOT, QKVN, DIM);
    // 2) kv partials per (b,h,split)
    kv_partial_kernel<<<dim3(BATCH * HEADS, NSPLIT), 256>>>(part_p);
    // 3) finalize + fold gammas -> C
    kv_finalize_kernel<<<BATCH * HEADS, DHEAD>>>(gamma);
    // 4) u = (q/||q||) @ C per head
    apply_kernel<<<dim3(BATCH * HEADS, NTOK / 64), 256>>>(u_p);
    // 5) out = u @ W_o + b_o       [16384,1024]x[1024,1024]
    sgemm_kernel<<<dim3(INNER / BN, MTOT / BM), 256>>>(u_p, W_o, b_o, out,
                                                       MTOT, INNER, DIM);
}

// round 4
// speedup vs baseline: 1.9701x; 1.9701x over previous
#include <cuda_runtime.h>
#include <cuda_bf16.h>
#include <math.h>
#include <stdint.h>

#define DIM     1024
#define HEADS   16
#define DHEAD   64
#define INNER   1024
#define BATCH   4
#define NTOK    4096
#define MTOT    (BATCH * NTOK)      // 16384
#define QKVN    (3 * INNER)         // 3072
#define NSPLIT  16

// ---------------------------------------------------------------------------
// Scratch (device globals; no runtime allocation allowed)
// ---------------------------------------------------------------------------
__device__ float g_qkv[(size_t)MTOT * QKVN];                                 // 192 MB
__device__ float g_part[(size_t)NSPLIT * BATCH * HEADS * DHEAD * DHEAD];     // 16 MB
__device__ float g_C[(size_t)BATCH * HEADS * DHEAD * DHEAD];                 // 1 MB
__device__ float g_u[(size_t)MTOT * INNER];                                  // 64 MB

// Packed bf16 hi/lo (row-major A [M][K]; transposed B [N][K])
__device__ __nv_bfloat16 g_xh[(size_t)MTOT * DIM];
__device__ __nv_bfloat16 g_xl[(size_t)MTOT * DIM];
__device__ __nv_bfloat16 g_uh[(size_t)MTOT * DIM];
__device__ __nv_bfloat16 g_ul[(size_t)MTOT * DIM];
__device__ __nv_bfloat16 g_wqh[(size_t)QKVN * DIM];   // [N=3072][K=1024]
__device__ __nv_bfloat16 g_wql[(size_t)QKVN * DIM];
__device__ __nv_bfloat16 g_woh[(size_t)INNER * DIM];  // [N=1024][K=1024]
__device__ __nv_bfloat16 g_wol[(size_t)INNER * DIM];

// ---------------------------------------------------------------------------
// helpers
// ---------------------------------------------------------------------------
__device__ __forceinline__ uint32_t smem_u32(const void* p) {
    uint32_t a;
    asm("{ .reg .u64 t; cvta.to.shared.u64 t, %1; cvt.u32.u64 %0, t; }"
        : "=r"(a) : "l"(p));
    return a;
}

__device__ __forceinline__ void cp_async16(uint32_t dst, const void* src) {
    asm volatile("cp.async.cg.shared.global [%0], [%1], 16;"
                 :: "r"(dst), "l"(src) : "memory");
}
__device__ __forceinline__ void cp_commit() {
    asm volatile("cp.async.commit_group;" ::: "memory");
}
template <int N>
__device__ __forceinline__ void cp_wait() {
    asm volatile("cp.async.wait_group %0;" :: "n"(N) : "memory");
}

__device__ __forceinline__ void ldm_x4(uint32_t& r0, uint32_t& r1,
                                       uint32_t& r2, uint32_t& r3, uint32_t a) {
    asm volatile("ldmatrix.sync.aligned.m8n8.x4.shared.b16 {%0,%1,%2,%3}, [%4];"
                 : "=r"(r0), "=r"(r1), "=r"(r2), "=r"(r3) : "r"(a));
}

__device__ __forceinline__ void mma_bf16(float& c0, float& c1, float& c2, float& c3,
                                         uint32_t a0, uint32_t a1, uint32_t a2, uint32_t a3,
                                         uint32_t b0, uint32_t b1) {
    asm volatile(
        "mma.sync.aligned.m16n8k16.row.col.f32.bf16.bf16.f32 "
        "{%0,%1,%2,%3}, {%4,%5,%6,%7}, {%8,%9}, {%0,%1,%2,%3};"
        : "+f"(c0), "+f"(c1), "+f"(c2), "+f"(c3)
        : "r"(a0), "r"(a1), "r"(a2), "r"(a3), "r"(b0), "r"(b1));
}

// ---------------------------------------------------------------------------
// bf16x3 GEMM via mma.sync: C[M,N] = A @ B^T (+bias)
// A streams: Ah/Al row-major [M][K]; B streams: Bth/Btl row-major [N][K].
// CTA tile 128x128, BK=32, 8 warps (4m x 2n), warp tile 32m x 64n.
// ---------------------------------------------------------------------------
#define BKC      32
#define ROWB     80                      // padded row bytes (40 bf16)
#define OPSZ     (128 * ROWB)            // 10240 B per operand tile
#define BUFSZ    (4 * OPSZ)              // 40960 B per buffer
#define GEMM_SMEM (2 * BUFSZ)            // 81920 B

__global__ __launch_bounds__(256, 1) void gemm_bf16x3_kernel(
    const __nv_bfloat16* __restrict__ Ah, const __nv_bfloat16* __restrict__ Al,
    const __nv_bfloat16* __restrict__ Bth, const __nv_bfloat16* __restrict__ Btl,
    float* __restrict__ C, const float* __restrict__ bias, int N, int K)
{
    extern __shared__ char smem[];
    const uint32_t sb = smem_u32(smem);
    const int tid = threadIdx.x;
    const int lane = tid & 31;
    const int wid = tid >> 5;
    const int wm = wid & 3;          // 0..3  (m)
    const int wn = wid >> 2;         // 0..1  (n)
    const int ntile = blockIdx.x;
    const int mtile = blockIdx.y;

    // ---- gmem -> smem assignment (cp.async, 16B each, 8 per thread/chunk)
    const int g = tid >> 6;          // operand 0..3 (Ah, Al, Bth, Btl)
    const int lt = tid & 63;
    const __nv_bfloat16* opsrc;
    if (g == 0)      opsrc = Ah  + (size_t)mtile * 128 * K;
    else if (g == 1) opsrc = Al  + (size_t)mtile * 128 * K;
    else if (g == 2) opsrc = Bth + (size_t)ntile * 128 * K;
    else             opsrc = Btl + (size_t)ntile * 128 * K;

    const int nchunks = K / BKC;

    auto issue_chunk = [&](int c, int buf) {
        const uint32_t dbase = sb + buf * BUFSZ + g * OPSZ;
#pragma unroll
        for (int i = 0; i < 8; i++) {
            int idx = lt + 64 * i;       // 0..511
            int row = idx >> 2;
            int seg = idx & 3;
            cp_async16(dbase + row * ROWB + seg * 16,
                       opsrc + (size_t)row * K + c * BKC + seg * 8);
        }
        cp_commit();
    };

    float acc[2][8][4];
#pragma unroll
    for (int im = 0; im < 2; im++)
#pragma unroll
        for (int jn = 0; jn < 8; jn++)
#pragma unroll
            for (int r = 0; r < 4; r++) acc[im][jn][r] = 0.f;

    // fragment smem addresses (per lane, fixed except kk/buf offsets)
    // A: tile=lane>>3 -> rowoff=(tile&1)*8+(lane&7), coladd=(tile>>1)*16B
    const int at_tile = lane >> 3;
    const int a_row = (at_tile & 1) * 8 + (lane & 7);
    const int a_cadd = (at_tile >> 1) * 16;
    // B: rowoff=(tile>>1)*8+(lane&7), coladd=(tile&1)*16B
    const int b_row = ((at_tile >> 1) * 8) + (lane & 7);
    const int b_cadd = (at_tile & 1) * 16;

    issue_chunk(0, 0);

    for (int c = 0; c < nchunks; c++) {
        const int buf = c & 1;
        if (c + 1 < nchunks) { issue_chunk(c + 1, buf ^ 1); cp_wait<1>(); }
        else                 { cp_wait<0>(); }
        __syncthreads();

        const uint32_t base = sb + buf * BUFSZ;
#pragma unroll
        for (int kk = 0; kk < 2; kk++) {
            const int kb = kk * 32;  // 16 elems = 32 bytes
            uint32_t ah[2][4], al[2][4], bh[4][4], bl[4][4];
#pragma unroll
            for (int im = 0; im < 2; im++) {
                uint32_t aoff = (uint32_t)(wm * 32 + im * 16 + a_row) * ROWB + kb + a_cadd;
                ldm_x4(ah[im][0], ah[im][1], ah[im][2], ah[im][3], base + 0 * OPSZ + aoff);
                ldm_x4(al[im][0], al[im][1], al[im][2], al[im][3], base + 1 * OPSZ + aoff);
            }
#pragma unroll
            for (int p = 0; p < 4; p++) {
                uint32_t boff = (uint32_t)(wn * 64 + p * 16 + b_row) * ROWB + kb + b_cadd;
                ldm_x4(bh[p][0], bh[p][1], bh[p][2], bh[p][3], base + 2 * OPSZ + boff);
                ldm_x4(bl[p][0], bl[p][1], bl[p][2], bl[p][3], base + 3 * OPSZ + boff);
            }
#pragma unroll
            for (int im = 0; im < 2; im++) {
#pragma unroll
                for (int jn = 0; jn < 8; jn++) {
                    const int p = jn >> 1, q = (jn & 1) * 2;
                    float* cc = acc[im][jn];
                    mma_bf16(cc[0], cc[1], cc[2], cc[3],
                             ah[im][0], ah[im][1], ah[im][2], ah[im][3],
                             bh[p][q], bh[p][q + 1]);
                    mma_bf16(cc[0], cc[1], cc[2], cc[3],
                             ah[im][0], ah[im][1], ah[im][2], ah[im][3],
                             bl[p][q], bl[p][q + 1]);
                    mma_bf16(cc[0], cc[1], cc[2], cc[3],
                             al[im][0], al[im][1], al[im][2], al[im][3],
                             bh[p][q], bh[p][q + 1]);
                }
            }
        }
        __syncthreads();
    }

    // ---- epilogue
    const int m0 = mtile * 128 + wm * 32;
    const int n0 = ntile * 128 + wn * 64;
#pragma unroll
    for (int im = 0; im < 2; im++) {
#pragma unroll
        for (int jn = 0; jn < 8; jn++) {
            const int row = m0 + im * 16 + (lane >> 2);
            const int col = n0 + jn * 8 + (lane & 3) * 2;
            float b0 = bias ? bias[col] : 0.f;
            float b1 = bias ? bias[col + 1] : 0.f;
            float2 v0 = {acc[im][jn][0] + b0, acc[im][jn][1] + b1};
            float2 v1 = {acc[im][jn][2] + b0, acc[im][jn][3] + b1};
            *reinterpret_cast<float2*>(C + (size_t)row * N + col) = v0;
            *reinterpret_cast<float2*>(C + (size_t)(row + 8) * N + col) = v1;
        }
    }
}

// ---------------------------------------------------------------------------
// packA: fp32 [M][K] -> hi/lo bf16 [M][K] (row-major). 8 elems/thread.
// ---------------------------------------------------------------------------
__global__ __launch_bounds__(256) void packA_kernel(
    const float* __restrict__ A, __nv_bfloat16* __restrict__ H,
    __nv_bfloat16* __restrict__ L)
{
    const size_t e0 = ((size_t)blockIdx.x * 256 + threadIdx.x) * 8;
    float4 v0 = *reinterpret_cast<const float4*>(A + e0);
    float4 v1 = *reinterpret_cast<const float4*>(A + e0 + 4);
    float f[8] = {v0.x, v0.y, v0.z, v0.w, v1.x, v1.y, v1.z, v1.w};
    ushort h[8], l[8];
#pragma unroll
    for (int i = 0; i < 8; i++) {
        __nv_bfloat16 hi = __float2bfloat16(f[i]);
        __nv_bfloat16 lo = __float2bfloat16(f[i] - __bfloat162float(hi));
        h[i] = __bfloat16_as_ushort(hi);
        l[i] = __bfloat16_as_ushort(lo);
    }
    *reinterpret_cast<uint4*>(H + e0) = *reinterpret_cast<uint4*>(h);
    *reinterpret_cast<uint4*>(L + e0) = *reinterpret_cast<uint4*>(l);
}

// ---------------------------------------------------------------------------
// packBt: fp32 W[K][N] -> hi/lo bf16 Bt[N][K] (transpose). 32x32 tiles.
// ---------------------------------------------------------------------------
__global__ __launch_bounds__(256) void packBt_kernel(
    const float* __restrict__ W, __nv_bfloat16* __restrict__ H,
    __nv_bfloat16* __restrict__ L, int N, int K)
{
    __shared__ float tile[32][33];
    const int k0 = blockIdx.x * 32;
    const int n0 = blockIdx.y * 32;
    const int x = threadIdx.x, y = threadIdx.y;  // block (32, 8)

#pragma unroll
    for (int r = 0; r < 4; r++) {
        int row = y + r * 8;
        tile[row][x] = W[(size_t)(k0 + row) * N + n0 + x];
    }
    __syncthreads();
#pragma unroll
    for (int r = 0; r < 4; r++) {
        int n = y + r * 8;                  // row of Bt within tile
        float f = tile[x][n];
        __nv_bfloat16 hi = __float2bfloat16(f);
        __nv_bfloat16 lo = __float2bfloat16(f - __bfloat162float(hi));
        size_t o = (size_t)(n0 + n) * K + k0 + x;
        H[o] = hi;
        L[o] = lo;
    }
}

// ---------------------------------------------------------------------------
// kv partial: kv[d][e] = sum_n k[n,d]*v[n,e] per (b,h,split)
// ---------------------------------------------------------------------------
#define KVCH 16

__global__ __launch_bounds__(256) void kv_partial_kernel(float* __restrict__ part)
{
    const int bh = blockIdx.x;
    const int split = blockIdx.y;
    const int b = bh / HEADS, h = bh % HEADS;
    const int n0 = split * (NTOK / NSPLIT);

    __shared__ float ks[KVCH][DHEAD];
    __shared__ float vs[KVCH][DHEAD];

    const int tid = threadIdx.x;
    const int tx = tid % 16, ty = tid / 16;

    float acc[4][4];
#pragma unroll
    for (int i = 0; i < 4; i++)
#pragma unroll
        for (int j = 0; j < 4; j++) acc[i][j] = 0.f;

    const float* base = g_qkv + (size_t)b * NTOK * QKVN;

    for (int n = n0; n < n0 + NTOK / NSPLIT; n += KVCH) {
        {
            int i = tid * 4;
            int r = i / DHEAD, c = i % DHEAD;
            const float* p = base + (size_t)(n + r) * QKVN + h * DHEAD + c;
            *reinterpret_cast<float4*>(&ks[r][c]) = *reinterpret_cast<const float4*>(p + INNER);
            *reinterpret_cast<float4*>(&vs[r][c]) = *reinterpret_cast<const float4*>(p + 2 * INNER);
        }
        __syncthreads();
#pragma unroll
        for (int nn = 0; nn < KVCH; nn++) {
            float rk[4], rv[4];
#pragma unroll
            for (int i = 0; i < 4; i++) rk[i] = ks[nn][ty * 4 + i];
#pragma unroll
            for (int j = 0; j < 4; j++) rv[j] = vs[nn][tx * 4 + j];
#pragma unroll
            for (int i = 0; i < 4; i++)
#pragma unroll
                for (int j = 0; j < 4; j++)
                    acc[i][j] += rk[i] * rv[j];
        }
        __syncthreads();
    }

    float* out = part + ((size_t)split * BATCH * HEADS + bh) * (DHEAD * DHEAD);
#pragma unroll
    for (int i = 0; i < 4; i++)
#pragma unroll
        for (int j = 0; j < 4; j++)
            out[(ty * 4 + i) * DHEAD + tx * 4 + j] = acc[i][j];
}

// ---------------------------------------------------------------------------
// kv finalize: C[d][e] = gamma_h^2 * kv[d][e] / ||kv[d,:]||
// ---------------------------------------------------------------------------
__global__ void kv_finalize_kernel(const float* __restrict__ gamma)
{
    const int bh = blockIdx.x;
    const int d = threadIdx.x;
    const int h = bh % HEADS;

    float row[DHEAD];
#pragma unroll
    for (int e = 0; e < DHEAD; e++) row[e] = 0.f;

    for (int s = 0; s < NSPLIT; s++) {
        const float* p = g_part + ((size_t)s * BATCH * HEADS + bh) * (DHEAD * DHEAD) + d * DHEAD;
#pragma unroll
        for (int e = 0; e < DHEAD; e++) row[e] += p[e];
    }
    float ss = 0.f;
#pragma unroll
    for (int e = 0; e < DHEAD; e++) ss += row[e] * row[e];

    const float g = gamma[h];
    const float scale = g * g / sqrtf(ss);

    float* out = g_C + (size_t)bh * DHEAD * DHEAD + d * DHEAD;
#pragma unroll
    for (int e = 0; e < DHEAD; e++) out[e] = row[e] * scale;
}

// ---------------------------------------------------------------------------
// apply: u[b,n, h*64+e] = (q[b,h,n,:] @ C[b,h]) / ||q[b,h,n,:]||
// ---------------------------------------------------------------------------
#define QPAD 68

__global__ __launch_bounds__(256) void apply_kernel(float* __restrict__ u)
{
    const int bh = blockIdx.x;
    const int chunk = blockIdx.y;
    const int b = bh / HEADS, h = bh % HEADS;

    __shared__ float Cs[DHEAD][DHEAD];
    __shared__ float qs[64][QPAD];
    __shared__ float inv[64];

    const int tid = threadIdx.x;
    const int n0 = chunk * 64;

#pragma unroll
    for (int i = tid * 4; i < DHEAD * DHEAD; i += 1024)
        *reinterpret_cast<float4*>(&Cs[0][0] + i) =
            *reinterpret_cast<const float4*>(g_C + (size_t)bh * DHEAD * DHEAD + i);

#pragma unroll
    for (int i = tid * 4; i < 64 * DHEAD; i += 1024) {
        int t = i / DHEAD, d = i % DHEAD;
        *reinterpret_cast<float4*>(&qs[t][d]) =
            *reinterpret_cast<const float4*>(g_qkv + (size_t)(b * NTOK + n0 + t) * QKVN + h * DHEAD + d);
    }
    __syncthreads();

    if (tid < 64) {
        float ss = 0.f;
#pragma unroll
        for (int d = 0; d < DHEAD; d++) { float x = qs[tid][d]; ss += x * x; }
        inv[tid] = 1.0f / sqrtf(ss);
    }
    __syncthreads();

    const int tx = tid % 16, ty = tid / 16;
    float acc[4][4];
#pragma unroll
    for (int i = 0; i < 4; i++)
#pragma unroll
        for (int j = 0; j < 4; j++) acc[i][j] = 0.f;

#pragma unroll
    for (int d = 0; d < DHEAD; d++) {
        float rq[4], rc[4];
#pragma unroll
        for (int i = 0; i < 4; i++) rq[i] = qs[ty * 4 + i][d];
#pragma unroll
        for (int j = 0; j < 4; j++) rc[j] = Cs[d][tx * 4 + j];
#pragma unroll
        for (int i = 0; i < 4; i++)
#pragma unroll
            for (int j = 0; j < 4; j++)
                acc[i][j] += rq[i] * rc[j];
    }

#pragma unroll
    for (int i = 0; i < 4; i++) {
        int t = ty * 4 + i;
        float s = inv[t];
        float4 o;
        o.x = acc[i][0] * s; o.y = acc[i][1] * s; o.z = acc[i][2] * s; o.w = acc[i][3] * s;
        *reinterpret_cast<float4*>(u + (size_t)(b * NTOK + n0 + t) * INNER + h * DHEAD + tx * 4) = o;
    }
}

// ---------------------------------------------------------------------------
extern "C" void kernel_launch(void* const* d_in, const int* in_sizes, int n_in,
                              void* d_out, int out_size)
{
    const float* x     = (const float*)d_in[0];
    const float* W_qkv = (const float*)d_in[1];
    const float* W_o   = (const float*)d_in[2];
    const float* b_o   = (const float*)d_in[3];
    const float* gamma = (const float*)d_in[4];
    float* out = (float*)d_out;

    static float* qkv_p = nullptr;
    static float* part_p = nullptr;
    static float* u_p = nullptr;
    static __nv_bfloat16 *xh, *xl, *uh, *ul, *wqh, *wql, *woh, *wol;
    if (!qkv_p) {
        cudaGetSymbolAddress((void**)&qkv_p, g_qkv);
        cudaGetSymbolAddress((void**)&part_p, g_part);
        cudaGetSymbolAddress((void**)&u_p, g_u);
        cudaGetSymbolAddress((void**)&xh, g_xh);
        cudaGetSymbolAddress((void**)&xl, g_xl);
        cudaGetSymbolAddress((void**)&uh, g_uh);
        cudaGetSymbolAddress((void**)&ul, g_ul);
        cudaGetSymbolAddress((void**)&wqh, g_wqh);
        cudaGetSymbolAddress((void**)&wql, g_wql);
        cudaGetSymbolAddress((void**)&woh, g_woh);
        cudaGetSymbolAddress((void**)&wol, g_wol);
        cudaFuncSetAttribute(gemm_bf16x3_kernel,
                             cudaFuncAttributeMaxDynamicSharedMemorySize, GEMM_SMEM);
    }

    // 1) pack x and W_qkv
    packA_kernel<<<(size_t)MTOT * DIM / 2048, 256>>>(x, xh, xl);
    packBt_kernel<<<dim3(DIM / 32, QKVN / 32), dim3(32, 8)>>>(W_qkv, wqh, wql, QKVN, DIM);

    // 2) qkv = x @ W_qkv  (bf16x3 mma.sync)
    gemm_bf16x3_kernel<<<dim3(QKVN / 128, MTOT / 128), 256, GEMM_SMEM>>>(
        xh, xl, wqh, wql, qkv_p, nullptr, QKVN, DIM);

    // 3) kv partials, finalize, apply
    kv_partial_kernel<<<dim3(BATCH * HEADS, NSPLIT), 256>>>(part_p);
    kv_finalize_kernel<<<BATCH * HEADS, DHEAD>>>(gamma);
    apply_kernel<<<dim3(BATCH * HEADS, NTOK / 64), 256>>>(u_p);

    // 4) pack u and W_o
    packA_kernel<<<(size_t)MTOT * DIM / 2048, 256>>>(u_p, uh, ul);
    packBt_kernel<<<dim3(DIM / 32, INNER / 32), dim3(32, 8)>>>(W_o, woh, wol, INNER, DIM);

    // 5) out = u @ W_o + b_o  (bf16x3 mma.sync)
    gemm_bf16x3_kernel<<<dim3(INNER / 128, MTOT / 128), 256, GEMM_SMEM>>>(
        uh, ul, woh, wol, out, b_o, INNER, DIM);
}

// round 6
// speedup vs baseline: 2.3914x; 1.2139x over previous
#include <cuda_runtime.h>
#include <cuda_bf16.h>
#include <math.h>
#include <stdint.h>

#define DIM     1024
#define HEADS   16
#define DHEAD   64
#define INNER   1024
#define BATCH   4
#define NTOK    4096
#define MTOT    (BATCH * NTOK)      // 16384
#define QKVN    (3 * INNER)         // 3072
#define NSPLIT  16

// ---------------------------------------------------------------------------
// Scratch (device globals; no runtime allocation allowed)
// ---------------------------------------------------------------------------
__device__ float g_qkv[(size_t)MTOT * QKVN];                                 // 192 MB
__device__ float g_part[(size_t)NSPLIT * BATCH * HEADS * DHEAD * DHEAD];     // 16 MB
__device__ float g_C[(size_t)BATCH * HEADS * DHEAD * DHEAD];                 // 1 MB

// Packed bf16 hi/lo (row-major A [M][K]; transposed B [N][K])
__device__ __nv_bfloat16 g_xh[(size_t)MTOT * DIM];
__device__ __nv_bfloat16 g_xl[(size_t)MTOT * DIM];
__device__ __nv_bfloat16 g_uh[(size_t)MTOT * DIM];
__device__ __nv_bfloat16 g_ul[(size_t)MTOT * DIM];
__device__ __nv_bfloat16 g_wqh[(size_t)QKVN * DIM];   // [N=3072][K=1024]
__device__ __nv_bfloat16 g_wql[(size_t)QKVN * DIM];
__device__ __nv_bfloat16 g_woh[(size_t)INNER * DIM];  // [N=1024][K=1024]
__device__ __nv_bfloat16 g_wol[(size_t)INNER * DIM];

// ---------------------------------------------------------------------------
// helpers
// ---------------------------------------------------------------------------
__device__ __forceinline__ uint32_t smem_u32(const void* p) {
    uint32_t a;
    asm("{ .reg .u64 t; cvta.to.shared.u64 t, %1; cvt.u32.u64 %0, t; }"
        : "=r"(a) : "l"(p));
    return a;
}

__device__ __forceinline__ void cp_async16(uint32_t dst, const void* src) {
    asm volatile("cp.async.cg.shared.global [%0], [%1], 16;"
                 :: "r"(dst), "l"(src) : "memory");
}
__device__ __forceinline__ void cp_commit() {
    asm volatile("cp.async.commit_group;" ::: "memory");
}
template <int N>
__device__ __forceinline__ void cp_wait() {
    asm volatile("cp.async.wait_group %0;" :: "n"(N) : "memory");
}

__device__ __forceinline__ void ldm_x4(uint32_t& r0, uint32_t& r1,
                                       uint32_t& r2, uint32_t& r3, uint32_t a) {
    asm volatile("ldmatrix.sync.aligned.m8n8.x4.shared.b16 {%0,%1,%2,%3}, [%4];"
                 : "=r"(r0), "=r"(r1), "=r"(r2), "=r"(r3) : "r"(a));
}

__device__ __forceinline__ void mma_bf16(float& c0, float& c1, float& c2, float& c3,
                                         uint32_t a0, uint32_t a1, uint32_t a2, uint32_t a3,
                                         uint32_t b0, uint32_t b1) {
    asm volatile(
        "mma.sync.aligned.m16n8k16.row.col.f32.bf16.bf16.f32 "
        "{%0,%1,%2,%3}, {%4,%5,%6,%7}, {%8,%9}, {%0,%1,%2,%3};"
        : "+f"(c0), "+f"(c1), "+f"(c2), "+f"(c3)
        : "r"(a0), "r"(a1), "r"(a2), "r"(a3), "r"(b0), "r"(b1));
}

__device__ __forceinline__ void split_bf16(float f, ushort& h, ushort& l) {
    __nv_bfloat16 hi = __float2bfloat16(f);
    __nv_bfloat16 lo = __float2bfloat16(f - __bfloat162float(hi));
    h = __bfloat16_as_ushort(hi);
    l = __bfloat16_as_ushort(lo);
}

// ---------------------------------------------------------------------------
// bf16x3 GEMM via mma.sync: C[M,N] = A @ B^T (+bias)
// CTA tile 128x128, BK=32, 8 warps (4m x 2n). 2 CTAs/SM for issue hiding.
// ---------------------------------------------------------------------------
#define BKC      32
#define ROWB     80                      // padded row bytes (40 bf16)
#define OPSZ     (128 * ROWB)            // 10240 B per operand tile
#define BUFSZ    (4 * OPSZ)              // 40960 B per buffer
#define GEMM_SMEM (2 * BUFSZ)            // 81920 B

__global__ __launch_bounds__(256, 2) void gemm_bf16x3_kernel(
    const __nv_bfloat16* __restrict__ Ah, const __nv_bfloat16* __restrict__ Al,
    const __nv_bfloat16* __restrict__ Bth, const __nv_bfloat16* __restrict__ Btl,
    float* __restrict__ C, const float* __restrict__ bias, int N, int K)
{
    extern __shared__ char smem[];
    const uint32_t sb = smem_u32(smem);
    const int tid = threadIdx.x;
    const int lane = tid & 31;
    const int wid = tid >> 5;
    const int wm = wid & 3;          // 0..3  (m)
    const int wn = wid >> 2;         // 0..1  (n)
    const int ntile = blockIdx.x;
    const int mtile = blockIdx.y;

    // ---- gmem -> smem assignment (cp.async, 16B each, 8 per thread/chunk)
    const int g = tid >> 6;          // operand 0..3 (Ah, Al, Bth, Btl)
    const int lt = tid & 63;
    const __nv_bfloat16* opsrc;
    if (g == 0)      opsrc = Ah  + (size_t)mtile * 128 * K;
    else if (g == 1) opsrc = Al  + (size_t)mtile * 128 * K;
    else if (g == 2) opsrc = Bth + (size_t)ntile * 128 * K;
    else             opsrc = Btl + (size_t)ntile * 128 * K;

    const int nchunks = K / BKC;

    auto issue_chunk = [&](int c, int buf) {
        const uint32_t dbase = sb + buf * BUFSZ + g * OPSZ;
#pragma unroll
        for (int i = 0; i < 8; i++) {
            int idx = lt + 64 * i;       // 0..511
            int row = idx >> 2;
            int seg = idx & 3;
            cp_async16(dbase + row * ROWB + seg * 16,
                       opsrc + (size_t)row * K + c * BKC + seg * 8);
        }
        cp_commit();
    };

    float acc[2][8][4];
#pragma unroll
    for (int im = 0; im < 2; im++)
#pragma unroll
        for (int jn = 0; jn < 8; jn++)
#pragma unroll
            for (int r = 0; r < 4; r++) acc[im][jn][r] = 0.f;

    const int at_tile = lane >> 3;
    const int a_row = (at_tile & 1) * 8 + (lane & 7);
    const int a_cadd = (at_tile >> 1) * 16;
    const int b_row = ((at_tile >> 1) * 8) + (lane & 7);
    const int b_cadd = (at_tile & 1) * 16;

    issue_chunk(0, 0);

    for (int c = 0; c < nchunks; c++) {
        const int buf = c & 1;
        if (c + 1 < nchunks) { issue_chunk(c + 1, buf ^ 1); cp_wait<1>(); }
        else                 { cp_wait<0>(); }
        __syncthreads();

        const uint32_t base = sb + buf * BUFSZ;
#pragma unroll
        for (int kk = 0; kk < 2; kk++) {
            const int kb = kk * 32;  // 16 elems = 32 bytes
            uint32_t ah[2][4], al[2][4], bh[4][4], bl[4][4];
#pragma unroll
            for (int im = 0; im < 2; im++) {
                uint32_t aoff = (uint32_t)(wm * 32 + im * 16 + a_row) * ROWB + kb + a_cadd;
                ldm_x4(ah[im][0], ah[im][1], ah[im][2], ah[im][3], base + 0 * OPSZ + aoff);
                ldm_x4(al[im][0], al[im][1], al[im][2], al[im][3], base + 1 * OPSZ + aoff);
            }
#pragma unroll
            for (int p = 0; p < 4; p++) {
                uint32_t boff = (uint32_t)(wn * 64 + p * 16 + b_row) * ROWB + kb + b_cadd;
                ldm_x4(bh[p][0], bh[p][1], bh[p][2], bh[p][3], base + 2 * OPSZ + boff);
                ldm_x4(bl[p][0], bl[p][1], bl[p][2], bl[p][3], base + 3 * OPSZ + boff);
            }
#pragma unroll
            for (int im = 0; im < 2; im++) {
#pragma unroll
                for (int jn = 0; jn < 8; jn++) {
                    const int p = jn >> 1, q = (jn & 1) * 2;
                    float* cc = acc[im][jn];
                    mma_bf16(cc[0], cc[1], cc[2], cc[3],
                             ah[im][0], ah[im][1], ah[im][2], ah[im][3],
                             bh[p][q], bh[p][q + 1]);
                    mma_bf16(cc[0], cc[1], cc[2], cc[3],
                             ah[im][0], ah[im][1], ah[im][2], ah[im][3],
                             bl[p][q], bl[p][q + 1]);
                    mma_bf16(cc[0], cc[1], cc[2], cc[3],
                             al[im][0], al[im][1], al[im][2], al[im][3],
                             bh[p][q], bh[p][q + 1]);
                }
            }
        }
        __syncthreads();
    }

    // ---- epilogue
    const int m0 = mtile * 128 + wm * 32;
    const int n0 = ntile * 128 + wn * 64;
#pragma unroll
    for (int im = 0; im < 2; im++) {
#pragma unroll
        for (int jn = 0; jn < 8; jn++) {
            const int row = m0 + im * 16 + (lane >> 2);
            const int col = n0 + jn * 8 + (lane & 3) * 2;
            float b0 = bias ? bias[col] : 0.f;
            float b1 = bias ? bias[col + 1] : 0.f;
            float2 v0 = {acc[im][jn][0] + b0, acc[im][jn][1] + b1};
            float2 v1 = {acc[im][jn][2] + b0, acc[im][jn][3] + b1};
            *reinterpret_cast<float2*>(C + (size_t)row * N + col) = v0;
            *reinterpret_cast<float2*>(C + (size_t)(row + 8) * N + col) = v1;
        }
    }
}

// ---------------------------------------------------------------------------
// packA: fp32 [M][K] -> hi/lo bf16 [M][K] (row-major). 8 elems/thread.
// ---------------------------------------------------------------------------
__global__ __launch_bounds__(256) void packA_kernel(
    const float* __restrict__ A, __nv_bfloat16* __restrict__ H,
    __nv_bfloat16* __restrict__ L)
{
    const size_t e0 = ((size_t)blockIdx.x * 256 + threadIdx.x) * 8;
    float4 v0 = *reinterpret_cast<const float4*>(A + e0);
    float4 v1 = *reinterpret_cast<const float4*>(A + e0 + 4);
    float f[8] = {v0.x, v0.y, v0.z, v0.w, v1.x, v1.y, v1.z, v1.w};
    ushort h[8], l[8];
#pragma unroll
    for (int i = 0; i < 8; i++) split_bf16(f[i], h[i], l[i]);
    *reinterpret_cast<uint4*>(H + e0) = *reinterpret_cast<uint4*>(h);
    *reinterpret_cast<uint4*>(L + e0) = *reinterpret_cast<uint4*>(l);
}

// ---------------------------------------------------------------------------
// packBt: fp32 W[K][N] -> hi/lo bf16 Bt[N][K] (transpose). 32x32 tiles.
// ---------------------------------------------------------------------------
__global__ __launch_bounds__(256) void packBt_kernel(
    const float* __restrict__ W, __nv_bfloat16* __restrict__ H,
    __nv_bfloat16* __restrict__ L, int N, int K)
{
    __shared__ float tile[32][33];
    const int k0 = blockIdx.x * 32;
    const int n0 = blockIdx.y * 32;
    const int x = threadIdx.x, y = threadIdx.y;  // block (32, 8)

#pragma unroll
    for (int r = 0; r < 4; r++) {
        int row = y + r * 8;
        tile[row][x] = W[(size_t)(k0 + row) * N + n0 + x];
    }
    __syncthreads();
#pragma unroll
    for (int r = 0; r < 4; r++) {
        int n = y + r * 8;
        float f = tile[x][n];
        ushort h, l;
        split_bf16(f, h, l);
        size_t o = (size_t)(n0 + n) * K + k0 + x;
        H[o] = __ushort_as_bfloat16(h);
        L[o] = __ushort_as_bfloat16(l);
    }
}

// ---------------------------------------------------------------------------
// kv partial: kv[d][e] = sum_n k[n,d]*v[n,e] per (b,h,split)
// cp.async double-buffered.
// ---------------------------------------------------------------------------
#define KVCH 16

__global__ __launch_bounds__(256) void kv_partial_kernel(float* __restrict__ part)
{
    const int bh = blockIdx.x;
    const int split = blockIdx.y;
    const int b = bh / HEADS, h = bh % HEADS;
    const int n0 = split * (NTOK / NSPLIT);
    const int nstages = (NTOK / NSPLIT) / KVCH;

    __shared__ float ks[2][KVCH][DHEAD];
    __shared__ float vs[2][KVCH][DHEAD];

    const int tid = threadIdx.x;
    const int tx = tid % 16, ty = tid / 16;

    const float* base = g_qkv + (size_t)b * NTOK * QKVN;

    // per-thread load slot: one float4 into each of ks, vs
    const int li = tid * 4;
    const int lr = li / DHEAD, lc = li % DHEAD;
    const uint32_t ks_a[2] = {smem_u32(&ks[0][lr][lc]), smem_u32(&ks[1][lr][lc])};
    const uint32_t vs_a[2] = {smem_u32(&vs[0][lr][lc]), smem_u32(&vs[1][lr][lc])};

    auto issue = [&](int s, int buf) {
        const float* p = base + (size_t)(n0 + s * KVCH + lr) * QKVN + h * DHEAD + lc;
        cp_async16(ks_a[buf], p + INNER);
        cp_async16(vs_a[buf], p + 2 * INNER);
        cp_commit();
    };

    float acc[4][4];
#pragma unroll
    for (int i = 0; i < 4; i++)
#pragma unroll
        for (int j = 0; j < 4; j++) acc[i][j] = 0.f;

    issue(0, 0);

    for (int s = 0; s < nstages; s++) {
        const int buf = s & 1;
        if (s + 1 < nstages) { issue(s + 1, buf ^ 1); cp_wait<1>(); }
        else                 { cp_wait<0>(); }
        __syncthreads();

#pragma unroll
        for (int nn = 0; nn < KVCH; nn++) {
            float rk[4], rv[4];
#pragma unroll
            for (int i = 0; i < 4; i++) rk[i] = ks[buf][nn][ty * 4 + i];
#pragma unroll
            for (int j = 0; j < 4; j++) rv[j] = vs[buf][nn][tx * 4 + j];
#pragma unroll
            for (int i = 0; i < 4; i++)
#pragma unroll
                for (int j = 0; j < 4; j++)
                    acc[i][j] += rk[i] * rv[j];
        }
        __syncthreads();
    }

    float* out = part + ((size_t)split * BATCH * HEADS + bh) * (DHEAD * DHEAD);
#pragma unroll
    for (int i = 0; i < 4; i++)
#pragma unroll
        for (int j = 0; j < 4; j++)
            out[(ty * 4 + i) * DHEAD + tx * 4 + j] = acc[i][j];
}

// ---------------------------------------------------------------------------
// kv finalize: C[d][e] = gamma_h^2 * kv[d][e] / ||kv[d,:]||
// ---------------------------------------------------------------------------
__global__ void kv_finalize_kernel(const float* __restrict__ gamma)
{
    const int bh = blockIdx.x;
    const int d = threadIdx.x;
    const int h = bh % HEADS;

    float row[DHEAD];
#pragma unroll
    for (int e = 0; e < DHEAD; e++) row[e] = 0.f;

    for (int s = 0; s < NSPLIT; s++) {
        const float* p = g_part + ((size_t)s * BATCH * HEADS + bh) * (DHEAD * DHEAD) + d * DHEAD;
#pragma unroll
        for (int e = 0; e < DHEAD; e++) row[e] += p[e];
    }
    float ss = 0.f;
#pragma unroll
    for (int e = 0; e < DHEAD; e++) ss += row[e] * row[e];

    const float g = gamma[h];
    const float scale = g * g / sqrtf(ss);

    float* out = g_C + (size_t)bh * DHEAD * DHEAD + d * DHEAD;
#pragma unroll
    for (int e = 0; e < DHEAD; e++) out[e] = row[e] * scale;
}

// ---------------------------------------------------------------------------
// apply: u[b,n, h*64+e] = (q[b,h,n,:] @ C[b,h]) / ||q[b,h,n,:]||
// FUSED PACK: writes u directly as bf16 hi/lo streams for GEMM2.
// ---------------------------------------------------------------------------
#define QPAD 68

__global__ __launch_bounds__(256) void apply_kernel(
    __nv_bfloat16* __restrict__ UH, __nv_bfloat16* __restrict__ UL)
{
    const int bh = blockIdx.x;
    const int chunk = blockIdx.y;
    const int b = bh / HEADS, h = bh % HEADS;

    __shared__ float Cs[DHEAD][DHEAD];
    __shared__ float qs[64][QPAD];
    __shared__ float inv[64];

    const int tid = threadIdx.x;
    const int n0 = chunk * 64;

#pragma unroll
    for (int i = tid * 4; i < DHEAD * DHEAD; i += 1024)
        *reinterpret_cast<float4*>(&Cs[0][0] + i) =
            *reinterpret_cast<const float4*>(g_C + (size_t)bh * DHEAD * DHEAD + i);

#pragma unroll
    for (int i = tid * 4; i < 64 * DHEAD; i += 1024) {
        int t = i / DHEAD, d = i % DHEAD;
        *reinterpret_cast<float4*>(&qs[t][d]) =
            *reinterpret_cast<const float4*>(g_qkv + (size_t)(b * NTOK + n0 + t) * QKVN + h * DHEAD + d);
    }
    __syncthreads();

    if (tid < 64) {
        float ss = 0.f;
#pragma unroll
        for (int d = 0; d < DHEAD; d++) { float x = qs[tid][d]; ss += x * x; }
        inv[tid] = 1.0f / sqrtf(ss);
    }
    __syncthreads();

    const int tx = tid % 16, ty = tid / 16;
    float acc[4][4];
#pragma unroll
    for (int i = 0; i < 4; i++)
#pragma unroll
        for (int j = 0; j < 4; j++) acc[i][j] = 0.f;

#pragma unroll
    for (int d = 0; d < DHEAD; d++) {
        float rq[4], rc[4];
#pragma unroll
        for (int i = 0; i < 4; i++) rq[i] = qs[ty * 4 + i][d];
#pragma unroll
        for (int j = 0; j < 4; j++) rc[j] = Cs[d][tx * 4 + j];
#pragma unroll
        for (int i = 0; i < 4; i++)
#pragma unroll
            for (int j = 0; j < 4; j++)
                acc[i][j] += rq[i] * rc[j];
    }

#pragma unroll
    for (int i = 0; i < 4; i++) {
        int t = ty * 4 + i;
        float s = inv[t];
        ushort hh[4], ll[4];
#pragma unroll
        for (int j = 0; j < 4; j++) split_bf16(acc[i][j] * s, hh[j], ll[j]);
        size_t o = (size_t)(b * NTOK + n0 + t) * INNER + h * DHEAD + tx * 4;
        *reinterpret_cast<uint2*>(UH + o) = *reinterpret_cast<uint2*>(hh);
        *reinterpret_cast<uint2*>(UL + o) = *reinterpret_cast<uint2*>(ll);
    }
}

// ---------------------------------------------------------------------------
extern "C" void kernel_launch(void* const* d_in, const int* in_sizes, int n_in,
                              void* d_out, int out_size)
{
    const float* x     = (const float*)d_in[0];
    const float* W_qkv = (const float*)d_in[1];
    const float* W_o   = (const float*)d_in[2];
    const float* b_o   = (const float*)d_in[3];
    const float* gamma = (const float*)d_in[4];
    float* out = (float*)d_out;

    static float* qkv_p = nullptr;
    static float* part_p = nullptr;
    static __nv_bfloat16 *xh, *xl, *uh, *ul, *wqh, *wql, *woh, *wol;
    if (!qkv_p) {
        cudaGetSymbolAddress((void**)&qkv_p, g_qkv);
        cudaGetSymbolAddress((void**)&part_p, g_part);
        cudaGetSymbolAddress((void**)&xh, g_xh);
        cudaGetSymbolAddress((void**)&xl, g_xl);
        cudaGetSymbolAddress((void**)&uh, g_uh);
        cudaGetSymbolAddress((void**)&ul, g_ul);
        cudaGetSymbolAddress((void**)&wqh, g_wqh);
        cudaGetSymbolAddress((void**)&wql, g_wql);
        cudaGetSymbolAddress((void**)&woh, g_woh);
        cudaGetSymbolAddress((void**)&wol, g_wol);
        cudaFuncSetAttribute(gemm_bf16x3_kernel,
                             cudaFuncAttributeMaxDynamicSharedMemorySize, GEMM_SMEM);
    }

    // 1) pack x and W_qkv
    packA_kernel<<<(size_t)MTOT * DIM / 2048, 256>>>(x, xh, xl);
    packBt_kernel<<<dim3(DIM / 32, QKVN / 32), dim3(32, 8)>>>(W_qkv, wqh, wql, QKVN, DIM);

    // 2) qkv = x @ W_qkv  (bf16x3 mma.sync)
    gemm_bf16x3_kernel<<<dim3(QKVN / 128, MTOT / 128), 256, GEMM_SMEM>>>(
        xh, xl, wqh, wql, qkv_p, nullptr, QKVN, DIM);

    // 3) kv partials, finalize, apply (apply emits packed u directly)
    kv_partial_kernel<<<dim3(BATCH * HEADS, NSPLIT), 256>>>(part_p);
    kv_finalize_kernel<<<BATCH * HEADS, DHEAD>>>(gamma);
    apply_kernel<<<dim3(BATCH * HEADS, NTOK / 64), 256>>>(uh, ul);

    // 4) pack W_o
    packBt_kernel<<<dim3(DIM / 32, INNER / 32), dim3(32, 8)>>>(W_o, woh, wol, INNER, DIM);

    // 5) out = u @ W_o + b_o  (bf16x3 mma.sync)
    gemm_bf16x3_kernel<<<dim3(INNER / 128, MTOT / 128), 256, GEMM_SMEM>>>(
        uh, ul, woh, wol, out, b_o, INNER, DIM);
}